// round 10
// baseline (speedup 1.0000x reference)
#include <cuda_runtime.h>
#include <cstdint>
#include <cstddef>

#define HDIM 2048
#define FDIM 7168
#define NE   8
#define TMAX 4096
#define STAGES 4
#define WELEM (NE * FDIM * HDIM)

// ---------------- device scratch ---------------------------------------------
__device__ int   g_cnt[NE];
__device__ int   g_tok[NE * TMAX];
__device__ float g_wt [NE * TMAX];
__device__ float g_h  [(size_t)NE * TMAX * FDIM];
__device__ float g_w1t[WELEM];
__device__ float g_w2t[WELEM];
__device__ float g_w3t[WELEM];
__device__ float g_xt [(size_t)TMAX * HDIM];

// ---------------- helpers ----------------------------------------------------
__device__ __forceinline__ uint32_t f2tf(float f) {
    uint32_t u;
    asm("cvt.rna.tf32.f32 %0, %1;" : "=r"(u) : "f"(f));
    return u;
}
__device__ __forceinline__ float f2tf_f(float f) { return __uint_as_float(f2tf(f)); }
__device__ __forceinline__ float silu_f(float x) { return x / (1.0f + __expf(-x)); }

__device__ __forceinline__ uint32_t smem_u32(const void* p) {
    uint32_t a;
    asm("{ .reg .u64 t; cvta.to.shared.u64 t, %1; cvt.u32.u64 %0, t; }" : "=r"(a) : "l"(p));
    return a;
}

__device__ __forceinline__ void mma_tf32(float c[4], const uint32_t a[4], const uint32_t b[2]) {
    asm volatile(
        "mma.sync.aligned.m16n8k8.row.col.f32.tf32.tf32.f32 "
        "{%0,%1,%2,%3}, {%4,%5,%6,%7}, {%8,%9}, {%0,%1,%2,%3};"
        : "+f"(c[0]), "+f"(c[1]), "+f"(c[2]), "+f"(c[3])
        : "r"(a[0]), "r"(a[1]), "r"(a[2]), "r"(a[3]), "r"(b[0]), "r"(b[1]));
}

// ---- bulk async copy (sm_90 feature set, not `a`-gated) ----
__device__ __forceinline__ void bulk_ld(uint32_t dst, const float* g, uint32_t bytes, uint32_t mbar) {
    asm volatile("cp.async.bulk.shared::cta.global.mbarrier::complete_tx::bytes [%0], [%1], %2, [%3];"
        :: "r"(dst), "l"(g), "r"(bytes), "r"(mbar) : "memory");
}
#define MBAR_INIT(a, cnt_) \
    asm volatile("mbarrier.init.shared.b64 [%0], %1;" :: "r"(a), "r"(cnt_) : "memory")
#define MBAR_INVAL(a) \
    asm volatile("mbarrier.inval.shared.b64 [%0];" :: "r"(a) : "memory")
#define MBAR_EXPECT(a, bytes) \
    asm volatile("mbarrier.arrive.expect_tx.shared.b64 _, [%0], %1;" :: "r"(a), "r"(bytes) : "memory")
#define MBAR_WAIT(a, par) do {                                                       \
    uint32_t _m = (a); uint32_t _p = (par); uint32_t _done;                          \
    asm volatile("{\n\t.reg .pred p;\n\t"                                            \
        "mbarrier.try_wait.parity.acquire.cta.shared::cta.b64 p, [%1], %2;\n\t"      \
        "selp.b32 %0, 1, 0, p;\n\t}" : "=r"(_done) : "r"(_m), "r"(_p) : "memory");   \
    if (!_done) {                                                                    \
        asm volatile("{\n\t.reg .pred P1;\n\t"                                       \
            "WL_%=:\n\t"                                                             \
            "mbarrier.try_wait.parity.acquire.cta.shared::cta.b64 P1, [%0], %1, 0x989680;\n\t" \
            "@P1 bra.uni WD_%=;\n\t"                                                 \
            "bra.uni WL_%=;\n\t"                                                     \
            "WD_%=:\n\t}" :: "r"(_m), "r"(_p) : "memory");                           \
    }                                                                                \
} while (0)

#define U(x) __float_as_uint(x)

// ---------------- kernel 0: zero out + counters ------------------------------
__global__ void zero_kernel(float* __restrict__ out, int n) {
    int idx = blockIdx.x * blockDim.x + threadIdx.x;
    if (idx < NE) g_cnt[idx] = 0;
    for (int i = idx; i < n; i += gridDim.x * blockDim.x) out[i] = 0.0f;
}

// ---------------- kernel 0b: tf32-RNA pre-round ------------------------------
__global__ void convert_kernel(const float* __restrict__ src, float* __restrict__ dst, int n4) {
    int idx = blockIdx.x * blockDim.x + threadIdx.x;
    const float4* s4 = (const float4*)src;
    float4* d4 = (float4*)dst;
    for (int i = idx; i < n4; i += gridDim.x * blockDim.x) {
        float4 v = s4[i];
        v.x = f2tf_f(v.x); v.y = f2tf_f(v.y); v.z = f2tf_f(v.z); v.w = f2tf_f(v.w);
        d4[i] = v;
    }
}

// ---------------- kernel 1: gating (top-2) -----------------------------------
__global__ void gate_kernel(const float* __restrict__ X, const float* __restrict__ GW) {
    const int t = blockIdx.x;
    __shared__ float xs[HDIM];
    __shared__ float logits[NE];
    const int tid = threadIdx.x;
    for (int i = tid; i < HDIM; i += 256) xs[i] = X[(size_t)t * HDIM + i];
    __syncthreads();
    const int warp = tid >> 5, lane = tid & 31;
    if (warp < NE) {
        const float* gw = GW + (size_t)warp * HDIM;
        float s = 0.0f;
        for (int i = lane; i < HDIM; i += 32) s += xs[i] * gw[i];
        #pragma unroll
        for (int o = 16; o; o >>= 1) s += __shfl_xor_sync(0xffffffffu, s, o);
        if (lane == 0) logits[warp] = s;
    }
    __syncthreads();
    if (tid == 0) {
        int i0 = 0; float l0 = logits[0];
        #pragma unroll
        for (int i = 1; i < NE; i++) if (logits[i] > l0) { l0 = logits[i]; i0 = i; }
        int i1 = -1; float l1 = -1e30f;
        #pragma unroll
        for (int i = 0; i < NE; i++) if (i != i0 && logits[i] > l1) { l1 = logits[i]; i1 = i; }
        float w0 = 1.0f / (1.0f + __expf(l1 - l0));
        float w1 = 1.0f - w0;
        int p0 = atomicAdd(&g_cnt[i0], 1);
        g_tok[i0 * TMAX + p0] = t; g_wt[i0 * TMAX + p0] = w0;
        int p1 = atomicAdd(&g_cnt[i1], 1);
        g_tok[i1 * TMAX + p1] = t; g_wt[i1 * TMAX + p1] = w1;
    }
}

// row stride in smem tiles: 36 words = 144 bytes (multiple of 16 for bulk)
#define RSTRIDE 36
#define RBYTES  144
#define STG_TX  49152u     // bytes per stage, both GEMMs (384 rows x 128B)

// ---------------- kernel 2: GEMM1  h = silu(X@w1^T) * (X@w3^T) ---------------
// CTA tile 128(M) x 128(F), 8 warps 2(M)x4(N), warp tile 64x32 for BOTH w1,w3
#define SM1_A  (STAGES * 128 * RSTRIDE)
#define SMEM1_BYTES (3 * SM1_A * 4)

__global__ __launch_bounds__(256, 1) void gemm1_kernel(
    const float* __restrict__ X,
    const float* __restrict__ W1,
    const float* __restrict__ W3)
{
    const int e   = blockIdx.z;
    const int cnt = g_cnt[e];
    const int m0  = blockIdx.x * 128;
    if (m0 >= cnt) return;
    const int n0  = blockIdx.y * 128;

    extern __shared__ float smem[];
    __shared__ alignas(8) unsigned long long mbar_s[STAGES];
    float* sA  = smem;
    float* sB1 = smem + SM1_A;
    float* sB3 = sB1 + SM1_A;
    #define A1(s,r,c)  sA [((s) * 128 + (r)) * RSTRIDE + (c)]
    #define B1(s,r,c)  sB1[((s) * 128 + (r)) * RSTRIDE + (c)]
    #define B3(s,r,c)  sB3[((s) * 128 + (r)) * RSTRIDE + (c)]

    const int tid  = threadIdx.x;
    const int lane = tid & 31, warp = tid >> 5;
    const int wm = warp & 1, wn = warp >> 1;    // 2(M) x 4(N)
    const int g  = lane >> 2, tg = lane & 3;

    const uint32_t mb_base = smem_u32(mbar_s);
    if (tid == 0) {
        #pragma unroll
        for (int s = 0; s < STAGES; s++) MBAR_INIT(mb_base + 8 * s, 1);
    }
    __syncthreads();

    float acc1[4][4][4] = {};
    float acc3[4][4][4] = {};

    const int*   tokp = g_tok + e * TMAX + m0;
    const float* W1e  = W1 + (size_t)e * FDIM * HDIM + (size_t)n0 * HDIM;
    const float* W3e  = W3 + (size_t)e * FDIM * HDIM + (size_t)n0 * HDIM;

    // per-thread bulk-load assignments: tid<128 -> A row tid + B1 row tid;
    // tid>=128 -> B3 row tid-128
    const int rA = tid & 127;
    const float* gA;    // A or B1 first source
    const float* gB;    // second source (tid<128 only: B1); else B3
    uint32_t dA, dB;
    if (tid < 128) {
        int tok = (m0 + rA < cnt) ? tokp[rA] : 0;
        gA = X + (size_t)tok * HDIM;
        gB = W1e + (size_t)rA * HDIM;
        dA = smem_u32(sA)  + (uint32_t)rA * RBYTES;
        dB = smem_u32(sB1) + (uint32_t)rA * RBYTES;
    } else {
        gA = W3e + (size_t)rA * HDIM;
        gB = 0;
        dA = smem_u32(sB3) + (uint32_t)rA * RBYTES;
        dB = 0;
    }
    const int nkt = HDIM / 32;   // 64

    #define LOADB1(s, kt) do {                                                   \
        uint32_t mb_ = mb_base + 8 * (s);                                        \
        if (tid == 0) MBAR_EXPECT(mb_, STG_TX);                                  \
        int k0_ = (kt) * 32;                                                     \
        uint32_t so_ = (uint32_t)(s) * 128 * RBYTES;                             \
        bulk_ld(dA + so_, gA + k0_, 128, mb_);                                   \
        if (tid < 128) bulk_ld(dB + so_, gB + k0_, 128, mb_);                    \
    } while (0)

    #pragma unroll
    for (int s = 0; s < STAGES - 1; s++) LOADB1(s, s);

    for (int it = 0; it < nkt; it++) {
        MBAR_WAIT(mb_base + 8 * (it & 3), (it >> 2) & 1);
        __syncthreads();

        int pf = it + STAGES - 1;
        if (pf < nkt) LOADB1((pf & 3), pf);

        const int s = it & 3;
        #pragma unroll
        for (int kk = 0; kk < 32; kk += 8) {
            uint32_t a[4][4];
            #pragma unroll
            for (int mi = 0; mi < 4; mi++) {
                int mr = wm * 64 + mi * 16;
                a[mi][0] = U(A1(s, mr + g,     kk + tg    ));
                a[mi][1] = U(A1(s, mr + g + 8, kk + tg    ));
                a[mi][2] = U(A1(s, mr + g,     kk + tg + 4));
                a[mi][3] = U(A1(s, mr + g + 8, kk + tg + 4));
            }
            #pragma unroll
            for (int ni = 0; ni < 4; ni++) {
                int nc = wn * 32 + ni * 8;
                uint32_t b1[2] = { U(B1(s, nc + g, kk + tg)), U(B1(s, nc + g, kk + tg + 4)) };
                uint32_t b3[2] = { U(B3(s, nc + g, kk + tg)), U(B3(s, nc + g, kk + tg + 4)) };
                #pragma unroll
                for (int mi = 0; mi < 4; mi++) {
                    mma_tf32(acc1[mi][ni], a[mi], b1);
                    mma_tf32(acc3[mi][ni], a[mi], b3);
                }
            }
        }
    }

    // epilogue: h = tf32_round(silu(acc1) * acc3) -> g_h
    #pragma unroll
    for (int mi = 0; mi < 4; mi++) {
        int mr = m0 + wm * 64 + mi * 16;
        int ra = mr + g, rb = mr + g + 8;
        #pragma unroll
        for (int ni = 0; ni < 4; ni++) {
            int c = n0 + wn * 32 + ni * 8 + tg * 2;
            if (ra < cnt) {
                size_t base = ((size_t)e * TMAX + ra) * FDIM + c;
                g_h[base    ] = f2tf_f(silu_f(acc1[mi][ni][0]) * acc3[mi][ni][0]);
                g_h[base + 1] = f2tf_f(silu_f(acc1[mi][ni][1]) * acc3[mi][ni][1]);
            }
            if (rb < cnt) {
                size_t base = ((size_t)e * TMAX + rb) * FDIM + c;
                g_h[base    ] = f2tf_f(silu_f(acc1[mi][ni][2]) * acc3[mi][ni][2]);
                g_h[base + 1] = f2tf_f(silu_f(acc1[mi][ni][3]) * acc3[mi][ni][3]);
            }
        }
    }

    __syncthreads();
    if (tid == 0) {
        #pragma unroll
        for (int s = 0; s < STAGES; s++) MBAR_INVAL(mb_base + 8 * s);
    }
}

// ---------------- kernel 3: GEMM2  out += wt * (h @ w2^T) --------------------
// CTA tile 128(M) x 256(N:H), 8 warps 2(M)x4(N), warp tile 64x64
#define SM2_A  (STAGES * 128 * RSTRIDE)
#define SM2_B  (STAGES * 256 * RSTRIDE)
#define SMEM2_BYTES ((SM2_A + SM2_B) * 4)

__global__ __launch_bounds__(256, 1) void gemm2_kernel(
    const float* __restrict__ W2, float* __restrict__ out)
{
    const int e   = blockIdx.z;
    const int cnt = g_cnt[e];
    const int m0  = blockIdx.x * 128;
    if (m0 >= cnt) return;
    const int n0  = blockIdx.y * 256;

    extern __shared__ float smem[];
    __shared__ alignas(8) unsigned long long mbar_s[STAGES];
    float* sA = smem;
    float* sB = smem + SM2_A;
    #define A2(s,r,c)  sA[((s) * 128 + (r)) * RSTRIDE + (c)]
    #define B2(s,r,c)  sB[((s) * 256 + (r)) * RSTRIDE + (c)]

    const int tid  = threadIdx.x;
    const int lane = tid & 31, warp = tid >> 5;
    const int wm = warp & 1, wn = warp >> 1;    // 2(M) x 4(N)
    const int g  = lane >> 2, tg = lane & 3;

    const uint32_t mb_base = smem_u32(mbar_s);
    if (tid == 0) {
        #pragma unroll
        for (int s = 0; s < STAGES; s++) MBAR_INIT(mb_base + 8 * s, 1);
    }
    __syncthreads();

    float acc[4][8][4] = {};

    const float* Ae  = g_h + ((size_t)e * TMAX + m0) * FDIM;
    const float* W2e = W2 + (size_t)e * HDIM * FDIM + (size_t)n0 * FDIM;

    // per-thread bulk rows: all 256 threads own B row tid; tid<128 also A row tid
    const float* gBr = W2e + (size_t)tid * FDIM;
    const uint32_t dBr = smem_u32(sB) + (uint32_t)tid * RBYTES;
    const float* gAr = Ae + (size_t)(tid & 127) * FDIM;
    const uint32_t dAr = smem_u32(sA) + (uint32_t)(tid & 127) * RBYTES;
    const int nkt = FDIM / 32; // 224

    #define LOADB2(s, kt) do {                                                   \
        uint32_t mb_ = mb_base + 8 * (s);                                        \
        if (tid == 0) MBAR_EXPECT(mb_, STG_TX);                                  \
        int k0_ = (kt) * 32;                                                     \
        bulk_ld(dBr + (uint32_t)(s) * 256 * RBYTES, gBr + k0_, 128, mb_);        \
        if (tid < 128)                                                           \
            bulk_ld(dAr + (uint32_t)(s) * 128 * RBYTES, gAr + k0_, 128, mb_);    \
    } while (0)

    #pragma unroll
    for (int s = 0; s < STAGES - 1; s++) LOADB2(s, s);

    for (int it = 0; it < nkt; it++) {
        MBAR_WAIT(mb_base + 8 * (it & 3), (it >> 2) & 1);
        __syncthreads();

        int pf = it + STAGES - 1;
        if (pf < nkt) LOADB2((pf & 3), pf);

        const int s = it & 3;
        #pragma unroll
        for (int kk = 0; kk < 32; kk += 8) {
            uint32_t a[4][4];
            #pragma unroll
            for (int mi = 0; mi < 4; mi++) {
                int mr = wm * 64 + mi * 16;
                a[mi][0] = U(A2(s, mr + g,     kk + tg    ));
                a[mi][1] = U(A2(s, mr + g + 8, kk + tg    ));
                a[mi][2] = U(A2(s, mr + g,     kk + tg + 4));
                a[mi][3] = U(A2(s, mr + g + 8, kk + tg + 4));
            }
            #pragma unroll
            for (int ni = 0; ni < 8; ni++) {
                int nc = wn * 64 + ni * 8;
                uint32_t b[2] = { U(B2(s, nc + g, kk + tg)), U(B2(s, nc + g, kk + tg + 4)) };
                #pragma unroll
                for (int mi = 0; mi < 4; mi++) {
                    mma_tf32(acc[mi][ni], a[mi], b);
                }
            }
        }
    }

    // epilogue: out[tok] += wt * acc (exactly 2 commutative adds/elem)
    #pragma unroll
    for (int mi = 0; mi < 4; mi++) {
        int mr = m0 + wm * 64 + mi * 16;
        int ra = mr + g, rb = mr + g + 8;
        int tok0 = 0, tok1 = 0; float wt0 = 0.0f, wt1 = 0.0f;
        if (ra < cnt) { tok0 = g_tok[e * TMAX + ra]; wt0 = g_wt[e * TMAX + ra]; }
        if (rb < cnt) { tok1 = g_tok[e * TMAX + rb]; wt1 = g_wt[e * TMAX + rb]; }
        #pragma unroll
        for (int ni = 0; ni < 8; ni++) {
            int c = n0 + wn * 64 + ni * 8 + tg * 2;
            if (ra < cnt) {
                atomicAdd(out + (size_t)tok0 * HDIM + c,     wt0 * acc[mi][ni][0]);
                atomicAdd(out + (size_t)tok0 * HDIM + c + 1, wt0 * acc[mi][ni][1]);
            }
            if (rb < cnt) {
                atomicAdd(out + (size_t)tok1 * HDIM + c,     wt1 * acc[mi][ni][2]);
                atomicAdd(out + (size_t)tok1 * HDIM + c + 1, wt1 * acc[mi][ni][3]);
            }
        }
    }

    __syncthreads();
    if (tid == 0) {
        #pragma unroll
        for (int s = 0; s < STAGES; s++) MBAR_INVAL(mb_base + 8 * s);
    }
}

// ---------------- launcher ---------------------------------------------------
extern "C" void kernel_launch(void* const* d_in, const int* in_sizes, int n_in,
                              void* d_out, int out_size) {
    const float* X  = (const float*)d_in[0];
    const float* GW = (const float*)d_in[1];
    const float* W1 = (const float*)d_in[2];
    const float* W2 = (const float*)d_in[3];
    const float* W3 = (const float*)d_in[4];
    float* out = (float*)d_out;

    int T = in_sizes[0] / HDIM;   // 4096
    if (T > TMAX) T = TMAX;

    cudaFuncSetAttribute(gemm1_kernel, cudaFuncAttributeMaxDynamicSharedMemorySize, SMEM1_BYTES);
    cudaFuncSetAttribute(gemm2_kernel, cudaFuncAttributeMaxDynamicSharedMemorySize, SMEM2_BYTES);

    zero_kernel<<<2048, 256>>>(out, out_size);

    float *w1t, *w2t, *w3t, *xt;
    cudaGetSymbolAddress((void**)&w1t, g_w1t);
    cudaGetSymbolAddress((void**)&w2t, g_w2t);
    cudaGetSymbolAddress((void**)&w3t, g_w3t);
    cudaGetSymbolAddress((void**)&xt,  g_xt);
    convert_kernel<<<2048, 256>>>(W1, w1t, WELEM / 4);
    convert_kernel<<<2048, 256>>>(W2, w2t, WELEM / 4);
    convert_kernel<<<2048, 256>>>(W3, w3t, WELEM / 4);
    convert_kernel<<<512,  256>>>(X,  xt,  (T * HDIM) / 4);

    gate_kernel<<<T, 256>>>(X, GW);

    int mt = (T + 127) / 128;
    dim3 grid1(mt, FDIM / 128, NE);
    gemm1_kernel<<<grid1, 256, SMEM1_BYTES>>>(xt, w1t, w3t);

    dim3 grid2(mt, HDIM / 256, NE);
    gemm2_kernel<<<grid2, 256, SMEM2_BYTES>>>(w2t, out);
}

// round 13
// speedup vs baseline: 1.4319x; 1.4319x over previous
#include <cuda_runtime.h>
#include <cstdint>
#include <cstddef>

#define HDIM 2048
#define FDIM 7168
#define NE   8
#define TMAX 4096
#define STAGES 4
#define WELEM (NE * FDIM * HDIM)

// ---------------- device scratch ---------------------------------------------
__device__ int   g_cnt[NE];
__device__ int   g_tok[NE * TMAX];
__device__ float g_wt [NE * TMAX];
__device__ float g_h  [(size_t)NE * TMAX * FDIM];
__device__ float g_w1t[WELEM];
__device__ float g_w2t[WELEM];
__device__ float g_w3t[WELEM];
__device__ float g_xt [(size_t)TMAX * HDIM];

// ---------------- helpers ----------------------------------------------------
__device__ __forceinline__ uint32_t f2tf(float f) {
    uint32_t u;
    asm("cvt.rna.tf32.f32 %0, %1;" : "=r"(u) : "f"(f));
    return u;
}
__device__ __forceinline__ float f2tf_f(float f) { return __uint_as_float(f2tf(f)); }
__device__ __forceinline__ float silu_f(float x) { return x / (1.0f + __expf(-x)); }

__device__ __forceinline__ void mma_tf32(float c[4], const uint32_t a[4], const uint32_t b[2]) {
    asm volatile(
        "mma.sync.aligned.m16n8k8.row.col.f32.tf32.tf32.f32 "
        "{%0,%1,%2,%3}, {%4,%5,%6,%7}, {%8,%9}, {%0,%1,%2,%3};"
        : "+f"(c[0]), "+f"(c[1]), "+f"(c[2]), "+f"(c[3])
        : "r"(a[0]), "r"(a[1]), "r"(a[2]), "r"(a[3]), "r"(b[0]), "r"(b[1]));
}

__device__ __forceinline__ void cp16(void* smem, const float* g) {
    uint32_t sa = (uint32_t)__cvta_generic_to_shared(smem);
    asm volatile("cp.async.cg.shared.global [%0], [%1], 16;" :: "r"(sa), "l"(g));
}
#define CP_COMMIT()  asm volatile("cp.async.commit_group;")
#define CP_WAIT(N)   asm volatile("cp.async.wait_group %0;" :: "n"(N))

#define U(x) __float_as_uint(x)

// ---------------- kernel 0: zero out + counters ------------------------------
__global__ void zero_kernel(float* __restrict__ out, int n) {
    int idx = blockIdx.x * blockDim.x + threadIdx.x;
    if (idx < NE) g_cnt[idx] = 0;
    for (int i = idx; i < n; i += gridDim.x * blockDim.x) out[i] = 0.0f;
}

// ---------------- kernel 0b: tf32-RNA pre-round ------------------------------
__global__ void convert_kernel(const float* __restrict__ src, float* __restrict__ dst, int n4) {
    int idx = blockIdx.x * blockDim.x + threadIdx.x;
    const float4* s4 = (const float4*)src;
    float4* d4 = (float4*)dst;
    for (int i = idx; i < n4; i += gridDim.x * blockDim.x) {
        float4 v = s4[i];
        v.x = f2tf_f(v.x); v.y = f2tf_f(v.y); v.z = f2tf_f(v.z); v.w = f2tf_f(v.w);
        d4[i] = v;
    }
}

// ---------------- kernel 1: gating (top-2) -----------------------------------
__global__ void gate_kernel(const float* __restrict__ X, const float* __restrict__ GW) {
    const int t = blockIdx.x;
    __shared__ float xs[HDIM];
    __shared__ float logits[NE];
    const int tid = threadIdx.x;
    for (int i = tid; i < HDIM; i += 256) xs[i] = X[(size_t)t * HDIM + i];
    __syncthreads();
    const int warp = tid >> 5, lane = tid & 31;
    if (warp < NE) {
        const float* gw = GW + (size_t)warp * HDIM;
        float s = 0.0f;
        for (int i = lane; i < HDIM; i += 32) s += xs[i] * gw[i];
        #pragma unroll
        for (int o = 16; o; o >>= 1) s += __shfl_xor_sync(0xffffffffu, s, o);
        if (lane == 0) logits[warp] = s;
    }
    __syncthreads();
    if (tid == 0) {
        int i0 = 0; float l0 = logits[0];
        #pragma unroll
        for (int i = 1; i < NE; i++) if (logits[i] > l0) { l0 = logits[i]; i0 = i; }
        int i1 = -1; float l1 = -1e30f;
        #pragma unroll
        for (int i = 0; i < NE; i++) if (i != i0 && logits[i] > l1) { l1 = logits[i]; i1 = i; }
        float w0 = 1.0f / (1.0f + __expf(l1 - l0));
        float w1 = 1.0f - w0;
        int p0 = atomicAdd(&g_cnt[i0], 1);
        g_tok[i0 * TMAX + p0] = t; g_wt[i0 * TMAX + p0] = w0;
        int p1 = atomicAdd(&g_cnt[i1], 1);
        g_tok[i1 * TMAX + p1] = t; g_wt[i1 * TMAX + p1] = w1;
    }
}

// row stride in smem tiles: 36 words = 144 bytes
#define RSTRIDE 36
#define RBYTES  144

// ---------------- kernel 2: GEMM1  h = silu(X@w1^T) * (X@w3^T) ---------------
// CTA tile 128(M) x 128(F), 8 warps 2(M)x4(N), warp tile 64x32 for BOTH w1,w3
#define SM1_A  (STAGES * 128 * RSTRIDE)
#define SMEM1_BYTES (3 * SM1_A * 4)

__global__ __launch_bounds__(256, 1) void gemm1_kernel(
    const float* __restrict__ X,
    const float* __restrict__ W1,
    const float* __restrict__ W3)
{
    const int e   = blockIdx.z;
    const int cnt = g_cnt[e];
    const int m0  = blockIdx.x * 128;
    if (m0 >= cnt) return;
    const int n0  = blockIdx.y * 128;

    extern __shared__ float smem[];
    float* sA  = smem;
    float* sB1 = smem + SM1_A;
    float* sB3 = sB1 + SM1_A;
    #define A1(s,r,c)  sA [((s) * 128 + (r)) * RSTRIDE + (c)]
    #define B1(s,r,c)  sB1[((s) * 128 + (r)) * RSTRIDE + (c)]
    #define B3(s,r,c)  sB3[((s) * 128 + (r)) * RSTRIDE + (c)]

    const int tid  = threadIdx.x;
    const int lane = tid & 31, warp = tid >> 5;
    const int wm = warp & 1, wn = warp >> 1;    // 2(M) x 4(N)
    const int g  = lane >> 2, tg = lane & 3;

    float acc1[4][4][4] = {};
    float acc3[4][4][4] = {};

    const int*   tokp = g_tok + e * TMAX + m0;
    const float* W1e  = W1 + (size_t)e * FDIM * HDIM + (size_t)n0 * HDIM;
    const float* W3e  = W3 + (size_t)e * FDIM * HDIM + (size_t)n0 * HDIM;

    const int c4 = (tid & 7) * 4;
    const int r0 = tid >> 3;                    // 0..31
    int arow[4]; const float* aptr[4];
    #pragma unroll
    for (int i = 0; i < 4; i++) {
        arow[i] = r0 + i * 32;
        int tok = (m0 + arow[i] < cnt) ? tokp[arow[i]] : 0;
        aptr[i] = X + (size_t)tok * HDIM + c4;
    }
    const int nkt = HDIM / 32;   // 64
    const int nph = nkt / 2;     // 32

    #define LOAD1(s, kt) do {                                                   \
        int k0_ = (kt) * 32;                                                    \
        _Pragma("unroll")                                                       \
        for (int i_ = 0; i_ < 4; i_++) {                                        \
            int r_ = r0 + i_ * 32;                                              \
            cp16(&A1(s, r_, c4), aptr[i_] + k0_);                               \
            cp16(&B1(s, r_, c4), W1e + (size_t)r_ * HDIM + k0_ + c4);           \
            cp16(&B3(s, r_, c4), W3e + (size_t)r_ * HDIM + k0_ + c4);           \
        }                                                                       \
    } while (0)

    // fragment load for step st (0..7) of phase p into buffer q
    #define FRAG1(q, p_, st) do {                                               \
        const int t_ = 2 * (p_) + ((st) >> 2);                                  \
        const int s_ = t_ & 3;                                                  \
        const int kk_ = ((st) & 3) * 8;                                         \
        _Pragma("unroll")                                                       \
        for (int mi = 0; mi < 4; mi++) {                                        \
            int mr = wm * 64 + mi * 16;                                         \
            af[q][mi][0] = U(A1(s_, mr + g,     kk_ + tg    ));                 \
            af[q][mi][1] = U(A1(s_, mr + g + 8, kk_ + tg    ));                 \
            af[q][mi][2] = U(A1(s_, mr + g,     kk_ + tg + 4));                 \
            af[q][mi][3] = U(A1(s_, mr + g + 8, kk_ + tg + 4));                 \
        }                                                                       \
        _Pragma("unroll")                                                       \
        for (int ni = 0; ni < 4; ni++) {                                        \
            int nc = wn * 32 + ni * 8;                                          \
            b1f[q][ni][0] = U(B1(s_, nc + g, kk_ + tg));                        \
            b1f[q][ni][1] = U(B1(s_, nc + g, kk_ + tg + 4));                    \
            b3f[q][ni][0] = U(B3(s_, nc + g, kk_ + tg));                        \
            b3f[q][ni][1] = U(B3(s_, nc + g, kk_ + tg + 4));                    \
        }                                                                       \
    } while (0)

    #pragma unroll
    for (int s = 0; s < STAGES; s++) { LOAD1(s, s); CP_COMMIT(); }

    for (int p = 0; p < nph; p++) {
        if (p == 0) { CP_WAIT(2); } else { CP_WAIT(0); }
        __syncthreads();

        if (p >= 1) {
            int t2 = 2 * p + 2, t3 = 2 * p + 3;
            if (t2 < nkt) { LOAD1((t2 & 3), t2); CP_COMMIT(); }
            if (t3 < nkt) { LOAD1((t3 & 3), t3); CP_COMMIT(); }
        }

        uint32_t af[2][4][4];
        uint32_t b1f[2][4][2], b3f[2][4][2];
        FRAG1(0, p, 0);
        #pragma unroll
        for (int st = 0; st < 8; st++) {
            const int cur = st & 1;
            if (st < 7) FRAG1(cur ^ 1, p, st + 1);
            #pragma unroll
            for (int ni = 0; ni < 4; ni++) {
                #pragma unroll
                for (int mi = 0; mi < 4; mi++) {
                    mma_tf32(acc1[mi][ni], af[cur][mi], b1f[cur][ni]);
                    mma_tf32(acc3[mi][ni], af[cur][mi], b3f[cur][ni]);
                }
            }
        }
    }

    // epilogue: h = tf32_round(silu(acc1) * acc3) -> g_h
    #pragma unroll
    for (int mi = 0; mi < 4; mi++) {
        int mr = m0 + wm * 64 + mi * 16;
        int ra = mr + g, rb = mr + g + 8;
        #pragma unroll
        for (int ni = 0; ni < 4; ni++) {
            int c = n0 + wn * 32 + ni * 8 + tg * 2;
            if (ra < cnt) {
                size_t base = ((size_t)e * TMAX + ra) * FDIM + c;
                g_h[base    ] = f2tf_f(silu_f(acc1[mi][ni][0]) * acc3[mi][ni][0]);
                g_h[base + 1] = f2tf_f(silu_f(acc1[mi][ni][1]) * acc3[mi][ni][1]);
            }
            if (rb < cnt) {
                size_t base = ((size_t)e * TMAX + rb) * FDIM + c;
                g_h[base    ] = f2tf_f(silu_f(acc1[mi][ni][2]) * acc3[mi][ni][2]);
                g_h[base + 1] = f2tf_f(silu_f(acc1[mi][ni][3]) * acc3[mi][ni][3]);
            }
        }
    }
}

// ---------------- kernel 3: GEMM2  out += wt * (h @ w2^T) --------------------
// CTA tile 128(M) x 256(N:H), 8 warps 2(M)x4(N), warp tile 64x64
#define SM2_A  (STAGES * 128 * RSTRIDE)
#define SM2_B  (STAGES * 256 * RSTRIDE)
#define SMEM2_BYTES ((SM2_A + SM2_B) * 4)

__global__ __launch_bounds__(256, 1) void gemm2_kernel(
    const float* __restrict__ W2, float* __restrict__ out)
{
    const int e   = blockIdx.z;
    const int cnt = g_cnt[e];
    const int m0  = blockIdx.x * 128;
    if (m0 >= cnt) return;
    const int n0  = blockIdx.y * 256;

    extern __shared__ float smem[];
    float* sA = smem;
    float* sB = smem + SM2_A;
    #define A2(s,r,c)  sA[((s) * 128 + (r)) * RSTRIDE + (c)]
    #define B2(s,r,c)  sB[((s) * 256 + (r)) * RSTRIDE + (c)]

    const int tid  = threadIdx.x;
    const int lane = tid & 31, warp = tid >> 5;
    const int wm = warp & 1, wn = warp >> 1;    // 2(M) x 4(N)
    const int g  = lane >> 2, tg = lane & 3;

    float acc[4][8][4] = {};

    const float* Ae  = g_h + ((size_t)e * TMAX + m0) * FDIM;
    const float* W2e = W2 + (size_t)e * HDIM * FDIM + (size_t)n0 * FDIM;
    const int c4 = (tid & 7) * 4;
    const int r0 = tid >> 3;   // 0..31
    const int nkt = FDIM / 32; // 224
    const int nph = nkt / 2;   // 112

    #define LOAD2(s, kt) do {                                                    \
        int k0_ = (kt) * 32;                                                     \
        _Pragma("unroll")                                                        \
        for (int i_ = 0; i_ < 4; i_++) {                                         \
            int r_ = r0 + i_ * 32;                                               \
            cp16(&A2(s, r_, c4), Ae + (size_t)r_ * FDIM + k0_ + c4);             \
        }                                                                        \
        _Pragma("unroll")                                                        \
        for (int i_ = 0; i_ < 8; i_++) {                                         \
            int r_ = r0 + i_ * 32;                                               \
            cp16(&B2(s, r_, c4), W2e + (size_t)r_ * FDIM + k0_ + c4);            \
        }                                                                        \
    } while (0)

    #define FRAG2(q, p_, st) do {                                                \
        const int t_ = 2 * (p_) + ((st) >> 2);                                   \
        const int s_ = t_ & 3;                                                   \
        const int kk_ = ((st) & 3) * 8;                                          \
        _Pragma("unroll")                                                        \
        for (int mi = 0; mi < 4; mi++) {                                         \
            int mr = wm * 64 + mi * 16;                                          \
            af[q][mi][0] = U(A2(s_, mr + g,     kk_ + tg    ));                  \
            af[q][mi][1] = U(A2(s_, mr + g + 8, kk_ + tg    ));                  \
            af[q][mi][2] = U(A2(s_, mr + g,     kk_ + tg + 4));                  \
            af[q][mi][3] = U(A2(s_, mr + g + 8, kk_ + tg + 4));                  \
        }                                                                        \
        _Pragma("unroll")                                                        \
        for (int ni = 0; ni < 8; ni++) {                                         \
            int nc = wn * 64 + ni * 8;                                           \
            bf[q][ni][0] = U(B2(s_, nc + g, kk_ + tg));                          \
            bf[q][ni][1] = U(B2(s_, nc + g, kk_ + tg + 4));                      \
        }                                                                        \
    } while (0)

    #pragma unroll
    for (int s = 0; s < STAGES; s++) { LOAD2(s, s); CP_COMMIT(); }

    for (int p = 0; p < nph; p++) {
        if (p == 0) { CP_WAIT(2); } else { CP_WAIT(0); }
        __syncthreads();

        if (p >= 1) {
            int t2 = 2 * p + 2, t3 = 2 * p + 3;
            if (t2 < nkt) { LOAD2((t2 & 3), t2); CP_COMMIT(); }
            if (t3 < nkt) { LOAD2((t3 & 3), t3); CP_COMMIT(); }
        }

        uint32_t af[2][4][4];
        uint32_t bf[2][8][2];
        FRAG2(0, p, 0);
        #pragma unroll
        for (int st = 0; st < 8; st++) {
            const int cur = st & 1;
            if (st < 7) FRAG2(cur ^ 1, p, st + 1);
            #pragma unroll
            for (int ni = 0; ni < 8; ni++) {
                #pragma unroll
                for (int mi = 0; mi < 4; mi++) {
                    mma_tf32(acc[mi][ni], af[cur][mi], bf[cur][ni]);
                }
            }
        }
    }

    // epilogue: out[tok] += wt * acc (exactly 2 commutative adds/elem)
    #pragma unroll
    for (int mi = 0; mi < 4; mi++) {
        int mr = m0 + wm * 64 + mi * 16;
        int ra = mr + g, rb = mr + g + 8;
        int tok0 = 0, tok1 = 0; float wt0 = 0.0f, wt1 = 0.0f;
        if (ra < cnt) { tok0 = g_tok[e * TMAX + ra]; wt0 = g_wt[e * TMAX + ra]; }
        if (rb < cnt) { tok1 = g_tok[e * TMAX + rb]; wt1 = g_wt[e * TMAX + rb]; }
        #pragma unroll
        for (int ni = 0; ni < 8; ni++) {
            int c = n0 + wn * 64 + ni * 8 + tg * 2;
            if (ra < cnt) {
                atomicAdd(out + (size_t)tok0 * HDIM + c,     wt0 * acc[mi][ni][0]);
                atomicAdd(out + (size_t)tok0 * HDIM + c + 1, wt0 * acc[mi][ni][1]);
            }
            if (rb < cnt) {
                atomicAdd(out + (size_t)tok1 * HDIM + c,     wt1 * acc[mi][ni][2]);
                atomicAdd(out + (size_t)tok1 * HDIM + c + 1, wt1 * acc[mi][ni][3]);
            }
        }
    }
}

// ---------------- launcher ---------------------------------------------------
extern "C" void kernel_launch(void* const* d_in, const int* in_sizes, int n_in,
                              void* d_out, int out_size) {
    const float* X  = (const float*)d_in[0];
    const float* GW = (const float*)d_in[1];
    const float* W1 = (const float*)d_in[2];
    const float* W2 = (const float*)d_in[3];
    const float* W3 = (const float*)d_in[4];
    float* out = (float*)d_out;

    int T = in_sizes[0] / HDIM;   // 4096
    if (T > TMAX) T = TMAX;

    cudaFuncSetAttribute(gemm1_kernel, cudaFuncAttributeMaxDynamicSharedMemorySize, SMEM1_BYTES);
    cudaFuncSetAttribute(gemm2_kernel, cudaFuncAttributeMaxDynamicSharedMemorySize, SMEM2_BYTES);

    zero_kernel<<<2048, 256>>>(out, out_size);

    float *w1t, *w2t, *w3t, *xt;
    cudaGetSymbolAddress((void**)&w1t, g_w1t);
    cudaGetSymbolAddress((void**)&w2t, g_w2t);
    cudaGetSymbolAddress((void**)&w3t, g_w3t);
    cudaGetSymbolAddress((void**)&xt,  g_xt);
    convert_kernel<<<2048, 256>>>(W1, w1t, WELEM / 4);
    convert_kernel<<<2048, 256>>>(W2, w2t, WELEM / 4);
    convert_kernel<<<2048, 256>>>(W3, w3t, WELEM / 4);
    convert_kernel<<<512,  256>>>(X,  xt,  (T * HDIM) / 4);

    gate_kernel<<<T, 256>>>(X, GW);

    int mt = (T + 127) / 128;
    dim3 grid1(mt, FDIM / 128, NE);
    gemm1_kernel<<<grid1, 256, SMEM1_BYTES>>>(xt, w1t, w3t);

    dim3 grid2(mt, HDIM / 256, NE);
    gemm2_kernel<<<grid2, 256, SMEM2_BYTES>>>(w2t, out);
}